// round 14
// baseline (speedup 1.0000x reference)
#include <cuda_runtime.h>
#include <cstddef>

// DPLoss: mean over B rows of [ sum_{j<len[i]} (pred[i,j]-log(align[i,j]))^2 / len[i] ]
// B=4096, T=2048, fp32, len ~ U[1,2048].
//
// R13 = R11 (best: 10.85us; flat single-wave grid over half-row units,
// unit/thread-level masked-load skip, ~34MB effective, 32 regs / 74.5% occ)
// + warp->position-block rotation: in iteration k, warp w handles vec4 block
// (w+k)&7 of the unit. Fixes R11's systematic 2.6x per-warp work skew
// (low-tid warps were live far more often than high-tid warps) while keeping
// accesses fully coalesced and register count unchanged.

#define B_ROWS   4096
#define T_COLS   2048
#define T_VEC4   (T_COLS / 4)         // 512 float4 per row
#define NTHREADS 256
#define NCTAS    1184                 // 148 SMs * 8 CTA/SM -> single wave
#define UNITS    (B_ROWS * 2)         // 8192 half-row units

__device__ float    g_acc   = 0.0f;
__device__ unsigned g_count = 0;

__global__ __launch_bounds__(NTHREADS, 8) void dploss_kernel(
    const float4* __restrict__ pred,
    const float4* __restrict__ align,
    const int* __restrict__ lens,
    float* __restrict__ out)
{
    const int tid  = threadIdx.x;
    const int wid  = tid >> 5;
    const int lane = tid & 31;

    float s = 0.0f;

    int u = blockIdx.x;
    #pragma unroll 1
    for (int k = 0; u < UNITS; ++k, u += NCTAS) {
        const int row   = u >> 1;
        const int len   = __ldg(lens + row);          // 16KB, L1-resident
        const int jbase = (u & 1) << 10;              // 0 or 1024
        if (jbase >= len) continue;                   // unit fully masked

        const int blk = (wid + k) & 7;                // rotated block per warp
        const int i   = ((u & 1) << 8) | (blk << 5) | lane;   // vec4 idx in row
        const int j   = i << 2;                       // element idx in row
        if (j >= len) continue;                       // this vec4 masked

        const size_t base = (size_t)row * T_VEC4 + i;
        float4 pv = pred[base];
        float4 av = align[base];

        float d0 = pv.x - __logf(av.x);
        float d1 = pv.y - __logf(av.y);
        float d2 = pv.z - __logf(av.z);
        float d3 = pv.w - __logf(av.w);

        float rs;
        if (j + 4 <= len) {                           // fully valid (common)
            rs = d0 * d0 + d1 * d1 + d2 * d2 + d3 * d3;
        } else {                                      // row's last vec4
            rs = d0 * d0;
            if (j + 1 < len) rs += d1 * d1;
            if (j + 2 < len) rs += d2 * d2;
            if (j + 3 < len) rs += d3 * d3;
        }

        s += rs * __fdividef(1.0f, (float)len);
    }

    // warp reduction
    #pragma unroll
    for (int off = 16; off > 0; off >>= 1)
        s += __shfl_down_sync(0xFFFFFFFFu, s, off);

    // block reduction across 8 warps
    __shared__ float warp_sums[NTHREADS / 32];
    const int lid = tid & 31;
    if (lid == 0) warp_sums[wid] = s;
    __syncthreads();

    if (wid == 0) {
        float v = (lid < NTHREADS / 32) ? warp_sums[lid] : 0.0f;
        #pragma unroll
        for (int off = 4; off > 0; off >>= 1)
            v += __shfl_down_sync(0xFFFFFFFFu, v, off);

        if (lid == 0) {
            atomicAdd(&g_acc, v);
            __threadfence();
            unsigned prev = atomicInc(&g_count, NCTAS - 1);
            if (prev == NCTAS - 1) {
                float total = atomicExch(&g_acc, 0.0f);   // read + reset for replay
                *out = total * (1.0f / (float)B_ROWS);
            }
        }
    }
}

extern "C" void kernel_launch(void* const* d_in, const int* in_sizes, int n_in,
                              void* d_out, int out_size)
{
    const float4* pred  = (const float4*)d_in[0];
    const float4* align = (const float4*)d_in[1];
    const int*    lens  = (const int*)d_in[2];
    float* out = (float*)d_out;

    dploss_kernel<<<NCTAS, NTHREADS>>>(pred, align, lens, out);
}